// round 10
// baseline (speedup 1.0000x reference)
#include <cuda_runtime.h>

// R10: warp-specialized 2-layer LSTM, parity-duplicated named barriers
// (B_W0/B_W1 for h1 RAW, B_R0/B_R1 for WAR backpressure) -- fixes the
// count-based phase-lapping deadlock of R8/R9. 147 CTAs x 512 thr.

typedef unsigned long long u64;

#define TT     512
#define NBR    14
#define NBP    16
#define NTH    512
#define BTOT   2048
#define NCTA   147
#define PITCH  104

#define B_W0 1
#define B_W1 2
#define B_R0 3
#define B_R1 4
#define B_I  5

__device__ __forceinline__ void bar_sync(int id, int cnt) {
    asm volatile("bar.sync %0, %1;" :: "r"(id), "r"(cnt) : "memory");
}
__device__ __forceinline__ void bar_arrive(int id, int cnt) {
    asm volatile("bar.arrive %0, %1;" :: "r"(id), "r"(cnt) : "memory");
}
__device__ __forceinline__ u64 pack2(float lo, float hi) {
    u64 r; asm("mov.b64 %0, {%1, %2};" : "=l"(r) : "f"(lo), "f"(hi)); return r;
}
__device__ __forceinline__ float2 unpack2(u64 a) {
    float2 r; asm("mov.b64 {%0, %1}, %2;" : "=f"(r.x), "=f"(r.y) : "l"(a)); return r;
}
__device__ __forceinline__ void fma2(u64 &d, u64 a, u64 b) {
    asm("fma.rn.f32x2 %0, %1, %2, %0;" : "+l"(d) : "l"(a), "l"(b));
}
__device__ __forceinline__ float tanhap(float x) {
    float r; asm("tanh.approx.f32 %0, %1;" : "=f"(r) : "f"(x)); return r;
}
__device__ __forceinline__ float shx(float v, int m) {
    return __shfl_xor_sync(0xffffffffu, v, m);
}

__global__ __launch_bounds__(NTH, 1)
void lstm_fused(const float* __restrict__ x,
                const float* __restrict__ Wih1, const float* __restrict__ Whh1,
                const float* __restrict__ bih1, const float* __restrict__ bhh1,
                const float* __restrict__ Wih2, const float* __restrict__ Whh2,
                const float* __restrict__ bih2, const float* __restrict__ bhh2,
                const float* __restrict__ fc1w, const float* __restrict__ fc1b,
                const float* __restrict__ fc2w, const float* __restrict__ fc2b,
                float* __restrict__ out)
{
    __shared__ __align__(16) float  hcat[2][NBP][PITCH];
    __shared__ __align__(16) float4 xchunk[2][32][NBP];
    __shared__ float sfc1w[512], sfc1b[16], sfc2w[16], sfc2b[1];

    const int tid  = threadIdx.x;
    const int lane = tid & 31;
    const int wid  = tid >> 5;
    const int b0   = blockIdx.x * NBR;
    const bool bvalid = (tid < NBR) && (b0 + tid < BTOT);

    // ---- smem init ----
    for (int i = tid; i < 2 * NBP * PITCH; i += NTH) ((float*)hcat)[i] = 0.f;
    for (int i = tid; i < 512;             i += NTH) sfc1w[i] = fc1w[i];
    if (tid < 16) sfc1b[tid] = fc1b[tid];
    if (tid < 16) sfc2w[tid] = fc2w[tid];
    if (tid == 0) sfc2b[0] = fc2b[0];
    if (tid < 128) {
        int buf = tid >> 6, tq = (tid >> 1) & 31, b = 14 + (tid & 1);
        xchunk[buf][tq][b] = make_float4(0.f, 0.f, 0.f, 0.f);
    }

    if (wid < 8) {
        // ================= Layer-1 warps (tid 0..255) =================
        const int wg    = wid;
        const int jslot = lane & 7;
        const int ks1   = lane >> 3;
        const int j1    = wg * 8 + jslot;

        u64 w1[4][8];
        float wxs[4], b1r[4];
        #pragma unroll
        for (int g = 0; g < 4; ++g) {
            const float sc = (g == 2) ? 1.f : 0.5f;
            const int r1 = g * 64 + j1;
            #pragma unroll
            for (int m = 0; m < 8; ++m) {
                int k = 16 * ks1 + 2 * m;
                w1[g][m] = pack2(sc * Whh1[r1 * 64 + k], sc * Whh1[r1 * 64 + k + 1]);
            }
            wxs[g] = sc * Wih1[r1 * 4 + ks1];
            b1r[g] = sc * (bih1[r1] + bhh1[r1]);
        }
        int ro1[4], rox[4];
        #pragma unroll
        for (int q = 0; q < 4; ++q) {
            ro1[q] = (ks1 ^ q) * PITCH + 16 * ks1;
            rox[q] = (ks1 ^ q) * 4 + ks1;
        }
        const int so1 = ks1 * PITCH + j1;

        auto loadchunk = [&](int buf, int tbase) {
            #pragma unroll 2
            for (int idx = tid; idx < 32 * NBR; idx += 256) {
                int b = idx >> 5, tq = idx & 31;
                float4 v = make_float4(0.f, 0.f, 0.f, 0.f);
                if (b0 + b < BTOT)
                    v = *(const float4*)(x + ((size_t)(b0 + b) * TT + tbase + tq) * 4);
                xchunk[buf][tq][b] = v;
            }
        };
        loadchunk(0, 0);

        float c1[4] = {0.f, 0.f, 0.f, 0.f};
        __syncthreads();

        for (int s = 0; s < TT; ++s) {
            bar_sync(B_I, 256);                 // L1-internal: STS(s-1) -> LDS(s)
            if (((s + 1) & 31) == 0 && (s + 1) < TT)
                loadchunk(((s + 1) >> 5) & 1, s + 1);

            const float* Ab = &hcat[(s + 1) & 1][0][0];   // h1(s-1)
            float*       Bb = &hcat[s & 1][0][0];         // h1(s) dest
            const float* Xb = (const float*)&xchunk[(s >> 5) & 1][s & 31][0];

            float hout[4];
            #pragma unroll
            for (int G = 0; G < 4; ++G) {
                u64 acc[4][4];
                #pragma unroll
                for (int g = 0; g < 4; ++g)
                    #pragma unroll
                    for (int q = 0; q < 4; ++q) acc[g][q] = 0ULL;

                #pragma unroll
                for (int m = 0; m < 4; ++m)
                    #pragma unroll
                    for (int q = 0; q < 4; ++q) {
                        ulonglong2 hh =
                            *(const ulonglong2*)(Ab + 4 * G * PITCH + ro1[q] + 4 * m);
                        #pragma unroll
                        for (int g = 0; g < 4; ++g) {
                            fma2(acc[g][q], w1[g][2 * m],     hh.x);
                            fma2(acc[g][q], w1[g][2 * m + 1], hh.y);
                        }
                    }

                float xv[4];
                #pragma unroll
                for (int q = 0; q < 4; ++q) xv[q] = Xb[16 * G + rox[q]];

                float raw[4];
                #pragma unroll
                for (int g = 0; g < 4; ++g) {
                    float r0, r1, r2, r3;
                    { float2 f = unpack2(acc[g][0]); r0 = f.x + f.y; }
                    { float2 f = unpack2(acc[g][1]); r1 = f.x + f.y; }
                    { float2 f = unpack2(acc[g][2]); r2 = f.x + f.y; }
                    { float2 f = unpack2(acc[g][3]); r3 = f.x + f.y; }
                    r0 = fmaf(wxs[g], xv[0], r0);
                    r1 = fmaf(wxs[g], xv[1], r1);
                    r2 = fmaf(wxs[g], xv[2], r2);
                    r3 = fmaf(wxs[g], xv[3], r3);
                    float t1 = r0 + shx(r1, 8);
                    float t2 = r2 + shx(r3, 8);
                    raw[g] = t1 + shx(t2, 16) + b1r[g];
                }
                float gi = fmaf(0.5f, tanhap(raw[0]), 0.5f);
                float gf = fmaf(0.5f, tanhap(raw[1]), 0.5f);
                float gg = tanhap(raw[2]);
                float go = fmaf(0.5f, tanhap(raw[3]), 0.5f);
                float c  = fmaf(gf, c1[G], gi * gg);
                c1[G] = c;
                hout[G] = go * tanhap(c);
            }

            if (s >= 2) bar_sync((s & 1) ? B_R1 : B_R0, 512);  // L2(s-2) reads done
            #pragma unroll
            for (int G = 0; G < 4; ++G)
                Bb[4 * G * PITCH + so1] = hout[G];
            bar_arrive((s & 1) ? B_W1 : B_W0, 512);            // h1(s) published
        }
    } else {
        // ================= Layer-2 warps (tid 256..511) =================
        const int wg  = wid - 8;
        const int js2 = lane & 3;
        const int ks2 = (lane >> 2) & 7;
        const int q2  = ks2 & 3;
        const int j2  = wg * 4 + js2;

        u64 w2[4][6];
        float b2r[4];
        #pragma unroll
        for (int g = 0; g < 4; ++g) {
            const float sc = (g == 2) ? 1.f : 0.5f;
            const int r2 = g * 32 + j2;
            #pragma unroll
            for (int m = 0; m < 6; ++m) {
                int k = 12 * ks2 + 2 * m;
                float lo = (k < 64)     ? Wih2[r2 * 64 + k]     : Whh2[r2 * 32 + k - 64];
                float hi = (k + 1 < 64) ? Wih2[r2 * 64 + k + 1] : Whh2[r2 * 32 + k - 63];
                w2[g][m] = pack2(sc * lo, sc * hi);
            }
            b2r[g] = sc * (bih2[r2] + bhh2[r2]);
        }
        int ro2[4];
        #pragma unroll
        for (int q = 0; q < 4; ++q)
            ro2[q] = (q2 ^ q) * PITCH + 12 * ks2;
        const int so2 = q2 * PITCH + 64 + j2;

        float c2[4] = {0.f, 0.f, 0.f, 0.f};
        __syncthreads();

        // slot u: read buf[u&1] (h1(u) | h2(u-1)); write h2(u) -> buf[(u+1)&1][64:96)
        for (int u = 0; u < TT; ++u) {
            bar_sync((u & 1) ? B_W1 : B_W0, 512);   // h1(u) published
            const float* Rb = &hcat[u & 1][0][0];
            float*       Wb = &hcat[(u + 1) & 1][0][0];

            float raw[4][4];
            #pragma unroll
            for (int G = 0; G < 4; ++G) {
                u64 acc[4][4];
                #pragma unroll
                for (int g = 0; g < 4; ++g)
                    #pragma unroll
                    for (int q = 0; q < 4; ++q) acc[g][q] = 0ULL;

                #pragma unroll
                for (int m = 0; m < 3; ++m)
                    #pragma unroll
                    for (int q = 0; q < 4; ++q) {
                        ulonglong2 hh =
                            *(const ulonglong2*)(Rb + 4 * G * PITCH + ro2[q] + 4 * m);
                        #pragma unroll
                        for (int g = 0; g < 4; ++g) {
                            fma2(acc[g][q], w2[g][2 * m],     hh.x);
                            fma2(acc[g][q], w2[g][2 * m + 1], hh.y);
                        }
                    }
                #pragma unroll
                for (int g = 0; g < 4; ++g) {
                    float r0, r1, r2, r3;
                    { float2 f = unpack2(acc[g][0]); r0 = f.x + f.y; }
                    { float2 f = unpack2(acc[g][1]); r1 = f.x + f.y; }
                    { float2 f = unpack2(acc[g][2]); r2 = f.x + f.y; }
                    { float2 f = unpack2(acc[g][3]); r3 = f.x + f.y; }
                    float t1 = r0 + shx(r1, 4);
                    float t2 = r2 + shx(r3, 4);
                    float tt = t1 + shx(t2, 8);
                    raw[G][g] = tt + shx(tt, 16) + b2r[g];
                }
            }
            if (u <= 509) bar_arrive((u & 1) ? B_R1 : B_R0, 512);  // reads done

            // tail (overlaps L1's next compute)
            #pragma unroll
            for (int G = 0; G < 4; ++G) {
                float gi = fmaf(0.5f, tanhap(raw[G][0]), 0.5f);
                float gf = fmaf(0.5f, tanhap(raw[G][1]), 0.5f);
                float gg = tanhap(raw[G][2]);
                float go = fmaf(0.5f, tanhap(raw[G][3]), 0.5f);
                float c  = fmaf(gf, c2[G], gi * gg);
                c2[G] = c;
                if (lane < 16)
                    Wb[4 * G * PITCH + so2] = go * tanhap(c);
            }
        }
    }

    __syncthreads();

    // ---- FC head: final h2(TT-1) in hcat[TT & 1][.][64:96) ----
    if (bvalid) {
        const float* hv = &hcat[TT & 1][tid][64];
        float o = sfc2b[0];
        #pragma unroll
        for (int f = 0; f < 16; ++f) {
            float acc = sfc1b[f];
            #pragma unroll
            for (int k = 0; k < 32; ++k)
                acc = fmaf(sfc1w[f * 32 + k], hv[k], acc);
            o = fmaf(sfc2w[f], fmaxf(acc, 0.f), o);
        }
        out[b0 + tid] = o;
    }
}

extern "C" void kernel_launch(void* const* d_in, const int* in_sizes, int n_in,
                              void* d_out, int out_size) {
    const float* x    = (const float*)d_in[0];
    const float* Wih1 = (const float*)d_in[1];
    const float* Whh1 = (const float*)d_in[2];
    const float* bih1 = (const float*)d_in[3];
    const float* bhh1 = (const float*)d_in[4];
    const float* Wih2 = (const float*)d_in[5];
    const float* Whh2 = (const float*)d_in[6];
    const float* bih2 = (const float*)d_in[7];
    const float* bhh2 = (const float*)d_in[8];
    const float* fc1w = (const float*)d_in[9];
    const float* fc1b = (const float*)d_in[10];
    const float* fc2w = (const float*)d_in[11];
    const float* fc2b = (const float*)d_in[12];
    float* out = (float*)d_out;

    lstm_fused<<<NCTA, NTH>>>(x, Wih1, Whh1, bih1, bhh1,
                              Wih2, Whh2, bih2, bhh2,
                              fc1w, fc1b, fc2w, fc2b, out);
}

// round 11
// speedup vs baseline: 1.1132x; 1.1132x over previous
#include <cuda_runtime.h>

// R11: R7 structure (proven 1563us) + exact-14-batch processing (no padded
// rows 14/15 in the FMA loops: 3 full scatter groups + one width-2 special
// group per layer, -12.5% main FMA) + bias folded into accumulator init.
// 147 CTAs x 512 thr, warp-specialized L1/L2, one __syncthreads per slot.

typedef unsigned long long u64;

#define TT     512
#define NBR    14
#define NBP    16
#define NTH    512
#define BTOT   2048
#define NCTA   147
#define PITCH  104

__device__ __forceinline__ u64 pack2(float lo, float hi) {
    u64 r; asm("mov.b64 %0, {%1, %2};" : "=l"(r) : "f"(lo), "f"(hi)); return r;
}
__device__ __forceinline__ float2 unpack2(u64 a) {
    float2 r; asm("mov.b64 {%0, %1}, %2;" : "=f"(r.x), "=f"(r.y) : "l"(a)); return r;
}
__device__ __forceinline__ void fma2(u64 &d, u64 a, u64 b) {
    asm("fma.rn.f32x2 %0, %1, %2, %0;" : "+l"(d) : "l"(a), "l"(b));
}
__device__ __forceinline__ float tanhap(float x) {
    float r; asm("tanh.approx.f32 %0, %1;" : "=f"(r) : "f"(x)); return r;
}
__device__ __forceinline__ float shx(float v, int m) {
    return __shfl_xor_sync(0xffffffffu, v, m);
}

__global__ __launch_bounds__(NTH, 1)
void lstm_fused(const float* __restrict__ x,
                const float* __restrict__ Wih1, const float* __restrict__ Whh1,
                const float* __restrict__ bih1, const float* __restrict__ bhh1,
                const float* __restrict__ Wih2, const float* __restrict__ Whh2,
                const float* __restrict__ bih2, const float* __restrict__ bhh2,
                const float* __restrict__ fc1w, const float* __restrict__ fc1b,
                const float* __restrict__ fc2w, const float* __restrict__ fc2b,
                float* __restrict__ out)
{
    __shared__ __align__(16) float  hcat[2][NBP][PITCH];
    __shared__ __align__(16) float4 xchunk[2][32][NBP];
    __shared__ float sfc1w[512], sfc1b[16], sfc2w[16], sfc2b[1];

    const int tid  = threadIdx.x;
    const int lane = tid & 31;
    const int wid  = tid >> 5;
    const int b0   = blockIdx.x * NBR;
    const bool bvalid = (tid < NBR) && (b0 + tid < BTOT);

    // ---- smem init ----
    for (int i = tid; i < 2 * NBP * PITCH; i += NTH) ((float*)hcat)[i] = 0.f;
    for (int i = tid; i < 512;             i += NTH) sfc1w[i] = fc1w[i];
    if (tid < 16) sfc1b[tid] = fc1b[tid];
    if (tid < 16) sfc2w[tid] = fc2w[tid];
    if (tid == 0) sfc2b[0] = fc2b[0];
    if (tid < 128) {
        int buf = tid >> 6, tq = (tid >> 1) & 31, b = 14 + (tid & 1);
        xchunk[buf][tq][b] = make_float4(0.f, 0.f, 0.f, 0.f);
    }

    if (wid < 8) {
        // ================= Layer-1 warps (tid 0..255) =================
        const int wg    = wid;
        const int jslot = lane & 7;
        const int ks1   = lane >> 3;          // k-quarter 0..3 (lane bits 3,4)
        const int j1    = wg * 8 + jslot;

        u64 w1[4][8];
        float wxs[4], b1r[4];
        #pragma unroll
        for (int g = 0; g < 4; ++g) {
            const float sc = (g == 2) ? 1.f : 0.5f;
            const int r1 = g * 64 + j1;
            #pragma unroll
            for (int m = 0; m < 8; ++m) {
                int k = 16 * ks1 + 2 * m;
                w1[g][m] = pack2(sc * Whh1[r1 * 64 + k], sc * Whh1[r1 * 64 + k + 1]);
            }
            wxs[g] = sc * Wih1[r1 * 4 + ks1];
            b1r[g] = sc * (bih1[r1] + bhh1[r1]);
        }
        int ro1[4], rox[4];
        #pragma unroll
        for (int q = 0; q < 4; ++q) {
            ro1[q] = (ks1 ^ q) * PITCH + 16 * ks1;
            rox[q] = (ks1 ^ q) * 4 + ks1;
        }
        const int so1  = ks1 * PITCH + j1;                       // full groups
        // special group (batches 12,13): width-2 scatter over ks1 bit0
        const int sb   = ks1 & 1;                                // own batch 12+sb
        int ro1s[2], roxs[2];
        #pragma unroll
        for (int q = 0; q < 2; ++q) {
            ro1s[q] = (12 + (sb ^ q)) * PITCH + 16 * ks1;
            roxs[q] = (12 + (sb ^ q)) * 4 + ks1;
        }
        const int so1s = (12 + sb) * PITCH + j1;

        auto loadchunk = [&](int buf, int tbase) {
            #pragma unroll 2
            for (int idx = tid; idx < 32 * NBR; idx += 256) {
                int b = idx >> 5, tq = idx & 31;
                float4 v = make_float4(0.f, 0.f, 0.f, 0.f);
                if (b0 + b < BTOT)
                    v = *(const float4*)(x + ((size_t)(b0 + b) * TT + tbase + tq) * 4);
                xchunk[buf][tq][b] = v;
            }
        };
        loadchunk(0, 0);

        float c1[3] = {0.f, 0.f, 0.f};
        float c1s   = 0.f;
        __syncthreads();

        for (int s = 0; s <= TT; ++s) {
            if (s < TT) {
                if (((s + 1) & 31) == 0 && (s + 1) < TT)
                    loadchunk(((s + 1) >> 5) & 1, s + 1);

                const float* Ab = &hcat[(s + 1) & 1][0][0];   // h1(s-1)
                float*       Bb = &hcat[s & 1][0][0];         // h1(s) dest
                const float* Xb = (const float*)&xchunk[(s >> 5) & 1][s & 31][0];

                // ---- full groups: batches 0..11 ----
                #pragma unroll
                for (int G = 0; G < 3; ++G) {
                    u64 acc[4][4];
                    #pragma unroll
                    for (int g = 0; g < 4; ++g) {
                        acc[g][0] = pack2(b1r[g], 0.f);       // bias folded in
                        acc[g][1] = 0ULL; acc[g][2] = 0ULL; acc[g][3] = 0ULL;
                    }
                    #pragma unroll
                    for (int m = 0; m < 4; ++m)
                        #pragma unroll
                        for (int q = 0; q < 4; ++q) {
                            ulonglong2 hh =
                                *(const ulonglong2*)(Ab + 4 * G * PITCH + ro1[q] + 4 * m);
                            #pragma unroll
                            for (int g = 0; g < 4; ++g) {
                                fma2(acc[g][q], w1[g][2 * m],     hh.x);
                                fma2(acc[g][q], w1[g][2 * m + 1], hh.y);
                            }
                        }
                    float xv[4];
                    #pragma unroll
                    for (int q = 0; q < 4; ++q) xv[q] = Xb[16 * G + rox[q]];

                    float raw[4];
                    #pragma unroll
                    for (int g = 0; g < 4; ++g) {
                        float r0, r1, r2, r3;
                        { float2 f = unpack2(acc[g][0]); r0 = f.x + f.y; }
                        { float2 f = unpack2(acc[g][1]); r1 = f.x + f.y; }
                        { float2 f = unpack2(acc[g][2]); r2 = f.x + f.y; }
                        { float2 f = unpack2(acc[g][3]); r3 = f.x + f.y; }
                        r0 = fmaf(wxs[g], xv[0], r0);
                        r1 = fmaf(wxs[g], xv[1], r1);
                        r2 = fmaf(wxs[g], xv[2], r2);
                        r3 = fmaf(wxs[g], xv[3], r3);
                        float t1 = r0 + shx(r1, 8);
                        float t2 = r2 + shx(r3, 8);
                        raw[g] = t1 + shx(t2, 16);
                    }
                    float gi = fmaf(0.5f, tanhap(raw[0]), 0.5f);
                    float gf = fmaf(0.5f, tanhap(raw[1]), 0.5f);
                    float gg = tanhap(raw[2]);
                    float go = fmaf(0.5f, tanhap(raw[3]), 0.5f);
                    float c  = fmaf(gf, c1[G], gi * gg);
                    c1[G] = c;
                    Bb[4 * G * PITCH + so1] = go * tanhap(c);
                }

                // ---- special group: batches 12,13 (width-2 scatter) ----
                {
                    u64 acc[4][2];
                    #pragma unroll
                    for (int g = 0; g < 4; ++g) { acc[g][0] = 0ULL; acc[g][1] = 0ULL; }
                    #pragma unroll
                    for (int m = 0; m < 4; ++m)
                        #pragma unroll
                        for (int q = 0; q < 2; ++q) {
                            ulonglong2 hh = *(const ulonglong2*)(Ab + ro1s[q] + 4 * m);
                            #pragma unroll
                            for (int g = 0; g < 4; ++g) {
                                fma2(acc[g][q], w1[g][2 * m],     hh.x);
                                fma2(acc[g][q], w1[g][2 * m + 1], hh.y);
                            }
                        }
                    float xv0 = Xb[roxs[0]], xv1 = Xb[roxs[1]];
                    float raw[4];
                    #pragma unroll
                    for (int g = 0; g < 4; ++g) {
                        float r0, r1;
                        { float2 f = unpack2(acc[g][0]); r0 = f.x + f.y; }
                        { float2 f = unpack2(acc[g][1]); r1 = f.x + f.y; }
                        r0 = fmaf(wxs[g], xv0, r0);
                        r1 = fmaf(wxs[g], xv1, r1);
                        float s1 = r0 + shx(r1, 8);       // k-slice pair {ks,ks^1}
                        raw[g] = s1 + shx(s1, 16) + b1r[g];   // + other k-half
                    }
                    float gi = fmaf(0.5f, tanhap(raw[0]), 0.5f);
                    float gf = fmaf(0.5f, tanhap(raw[1]), 0.5f);
                    float gg = tanhap(raw[2]);
                    float go = fmaf(0.5f, tanhap(raw[3]), 0.5f);
                    float c  = fmaf(gf, c1s, gi * gg);
                    c1s = c;
                    if (ks1 < 2)
                        Bb[so1s] = go * tanhap(c);
                }
            }
            __syncthreads();
        }
    } else {
        // ================= Layer-2 warps (tid 256..511) =================
        const int wg  = wid - 8;
        const int js2 = lane & 3;
        const int ks2 = (lane >> 2) & 7;      // k-eighth (lane bits 2,3,4)
        const int q2  = ks2 & 3;
        const int j2  = wg * 4 + js2;

        u64 w2[4][6];
        float b2r[4];
        #pragma unroll
        for (int g = 0; g < 4; ++g) {
            const float sc = (g == 2) ? 1.f : 0.5f;
            const int r2 = g * 32 + j2;
            #pragma unroll
            for (int m = 0; m < 6; ++m) {
                int k = 12 * ks2 + 2 * m;
                float lo = (k < 64)     ? Wih2[r2 * 64 + k]     : Whh2[r2 * 32 + k - 64];
                float hi = (k + 1 < 64) ? Wih2[r2 * 64 + k + 1] : Whh2[r2 * 32 + k - 63];
                w2[g][m] = pack2(sc * lo, sc * hi);
            }
            b2r[g] = sc * (bih2[r2] + bhh2[r2]);
        }
        int ro2[4];
        #pragma unroll
        for (int q = 0; q < 4; ++q)
            ro2[q] = (q2 ^ q) * PITCH + 12 * ks2;
        const int so2  = q2 * PITCH + 64 + j2;
        // special group (batches 12,13): width-2 scatter over q2 bit0
        const int sb2  = q2 & 1;                              // own batch 12+sb2
        int ro2s[2];
        #pragma unroll
        for (int q = 0; q < 2; ++q)
            ro2s[q] = (12 + (sb2 ^ q)) * PITCH + 12 * ks2;
        const int so2s = (12 + sb2) * PITCH + 64 + j2;

        float c2[3] = {0.f, 0.f, 0.f};
        float c2s   = 0.f;
        __syncthreads();

        // slot s computes h2(s-1): reads hcat[(s+1)&1] (h1(s-1)|h2(s-2)),
        // writes h2(s-1) -> hcat[s&1][64:96)
        for (int s = 0; s <= TT; ++s) {
            if (s >= 1) {
                const float* Rb = &hcat[(s + 1) & 1][0][0];
                float*       Wb = &hcat[s & 1][0][0];

                // ---- full groups: batches 0..11 ----
                #pragma unroll
                for (int G = 0; G < 3; ++G) {
                    u64 acc[4][4];
                    #pragma unroll
                    for (int g = 0; g < 4; ++g) {
                        acc[g][0] = pack2(0.5f * b2r[g], 0.f);  // half-bias (tree doubles)
                        acc[g][1] = 0ULL; acc[g][2] = 0ULL; acc[g][3] = 0ULL;
                    }
                    #pragma unroll
                    for (int m = 0; m < 3; ++m)
                        #pragma unroll
                        for (int q = 0; q < 4; ++q) {
                            ulonglong2 hh =
                                *(const ulonglong2*)(Rb + 4 * G * PITCH + ro2[q] + 4 * m);
                            #pragma unroll
                            for (int g = 0; g < 4; ++g) {
                                fma2(acc[g][q], w2[g][2 * m],     hh.x);
                                fma2(acc[g][q], w2[g][2 * m + 1], hh.y);
                            }
                        }
                    float raw[4];
                    #pragma unroll
                    for (int g = 0; g < 4; ++g) {
                        float r0, r1, r2, r3;
                        { float2 f = unpack2(acc[g][0]); r0 = f.x + f.y; }
                        { float2 f = unpack2(acc[g][1]); r1 = f.x + f.y; }
                        { float2 f = unpack2(acc[g][2]); r2 = f.x + f.y; }
                        { float2 f = unpack2(acc[g][3]); r3 = f.x + f.y; }
                        float t1 = r0 + shx(r1, 4);
                        float t2 = r2 + shx(r3, 4);
                        float tt = t1 + shx(t2, 8);
                        raw[g] = tt + shx(tt, 16);
                    }
                    float gi = fmaf(0.5f, tanhap(raw[0]), 0.5f);
                    float gf = fmaf(0.5f, tanhap(raw[1]), 0.5f);
                    float gg = tanhap(raw[2]);
                    float go = fmaf(0.5f, tanhap(raw[3]), 0.5f);
                    float c  = fmaf(gf, c2[G], gi * gg);
                    c2[G] = c;
                    if (lane < 16)
                        Wb[4 * G * PITCH + so2] = go * tanhap(c);
                }

                // ---- special group: batches 12,13 ----
                {
                    u64 acc[4][2];
                    #pragma unroll
                    for (int g = 0; g < 4; ++g) { acc[g][0] = 0ULL; acc[g][1] = 0ULL; }
                    #pragma unroll
                    for (int m = 0; m < 3; ++m)
                        #pragma unroll
                        for (int q = 0; q < 2; ++q) {
                            ulonglong2 hh = *(const ulonglong2*)(Rb + ro2s[q] + 4 * m);
                            #pragma unroll
                            for (int g = 0; g < 4; ++g) {
                                fma2(acc[g][q], w2[g][2 * m],     hh.x);
                                fma2(acc[g][q], w2[g][2 * m + 1], hh.y);
                            }
                        }
                    float raw[4];
                    #pragma unroll
                    for (int g = 0; g < 4; ++g) {
                        float r0, r1;
                        { float2 f = unpack2(acc[g][0]); r0 = f.x + f.y; }
                        { float2 f = unpack2(acc[g][1]); r1 = f.x + f.y; }
                        float s1 = r0 + shx(r1, 4);      // slices {ks2, ks2^1}
                        float s2 = s1 + shx(s1, 8);      // + {ks2^2, ks2^3}
                        raw[g] = s2 + shx(s2, 16) + b2r[g];  // + other 4 slices
                    }
                    float gi = fmaf(0.5f, tanhap(raw[0]), 0.5f);
                    float gf = fmaf(0.5f, tanhap(raw[1]), 0.5f);
                    float gg = tanhap(raw[2]);
                    float go = fmaf(0.5f, tanhap(raw[3]), 0.5f);
                    float c  = fmaf(gf, c2s, gi * gg);
                    c2s = c;
                    if (ks2 < 2)
                        Wb[so2s] = go * tanhap(c);
                }
            }
            __syncthreads();
        }
    }

    __syncthreads();

    // ---- FC head: final h2(TT-1) in hcat[TT & 1][.][64:96) ----
    if (bvalid) {
        const float* hv = &hcat[TT & 1][tid][64];
        float o = sfc2b[0];
        #pragma unroll
        for (int f = 0; f < 16; ++f) {
            float acc = sfc1b[f];
            #pragma unroll
            for (int k = 0; k < 32; ++k)
                acc = fmaf(sfc1w[f * 32 + k], hv[k], acc);
            o = fmaf(sfc2w[f], fmaxf(acc, 0.f), o);
        }
        out[b0 + tid] = o;
    }
}

extern "C" void kernel_launch(void* const* d_in, const int* in_sizes, int n_in,
                              void* d_out, int out_size) {
    const float* x    = (const float*)d_in[0];
    const float* Wih1 = (const float*)d_in[1];
    const float* Whh1 = (const float*)d_in[2];
    const float* bih1 = (const float*)d_in[3];
    const float* bhh1 = (const float*)d_in[4];
    const float* Wih2 = (const float*)d_in[5];
    const float* Whh2 = (const float*)d_in[6];
    const float* bih2 = (const float*)d_in[7];
    const float* bhh2 = (const float*)d_in[8];
    const float* fc1w = (const float*)d_in[9];
    const float* fc1b = (const float*)d_in[10];
    const float* fc2w = (const float*)d_in[11];
    const float* fc2b = (const float*)d_in[12];
    float* out = (float*)d_out;

    lstm_fused<<<NCTA, NTH>>>(x, Wih1, Whh1, bih1, bhh1,
                              Wih2, Whh2, bih2, bhh2,
                              fc1w, fc1b, fc2w, fc2b, out);
}